// round 15
// baseline (speedup 1.0000x reference)
#include <cuda_runtime.h>
#include <math.h>

#define NBATCH 256
#define NH 128
#define NB 37
#define TSTEPS 12

// ---------------- scratch (device globals; no allocation, NO align attrs) ----------------
static __device__ float g_p1[(size_t)NBATCH * 30 * 90 * 64];   // 177 MB
static __device__ float g_p2[(size_t)NBATCH * 15 * 45 * 128];  //  88 MB
static __device__ float g_p3[(size_t)NBATCH * 8 * 23 * 128];   //  24 MB
static __device__ float g_p4[(size_t)NBATCH * 4 * 12 * 64];    //   3 MB
// Winograd weights U = G g G^T, ci-paired lanes:
// float index (((k)*(CIN/2)+cp)*COUT+co)*2 + (ci&1), k = 4*row+col
static __device__ float g_uw2[16 * 32 * 128 * 2];   // conv2 (1 MB)
static __device__ float g_uw3[16 * 64 * 128 * 2];   // conv3 (2 MB)

// ---------------- packed fp32x2 FMA (sm_100+) ----------------
__device__ __forceinline__ float2 ffma2(float2 a, float2 b, float2 c)
{
    float2 d;
    asm("fma.rn.f32x2 %0, %1, %2, %3;"
        : "=l"(reinterpret_cast<unsigned long long&>(d))
        : "l"(reinterpret_cast<unsigned long long&>(a)),
          "l"(reinterpret_cast<unsigned long long&>(b)),
          "l"(reinterpret_cast<unsigned long long&>(c)));
    return d;
}
__device__ __forceinline__ float2 fadd2(float2 a, float2 b) { return make_float2(a.x + b.x, a.y + b.y); }
__device__ __forceinline__ float2 fsub2(float2 a, float2 b) { return make_float2(a.x - b.x, a.y - b.y); }
__device__ __forceinline__ float sigm(float x) { return 1.f / (1.f + expf(-x)); }

// ---------------- Winograd weight transform: one (ci, cout) item, scalar-only ----------------
__device__ __forceinline__ void wino_xform_one(
    const float* __restrict__ w, float* __restrict__ uwf, int CIN, int COUT, int idx)
{
    int co = idx % COUT;
    int ci = idx / COUT;
    int cp = ci >> 1;
    int lane = ci & 1;

    float w0 = w[(size_t)(0 * CIN + ci) * COUT + co];
    float w1 = w[(size_t)(1 * CIN + ci) * COUT + co];
    float w2 = w[(size_t)(2 * CIN + ci) * COUT + co];
    float w3 = w[(size_t)(3 * CIN + ci) * COUT + co];
    float w4 = w[(size_t)(4 * CIN + ci) * COUT + co];
    float w5 = w[(size_t)(5 * CIN + ci) * COUT + co];
    float w6 = w[(size_t)(6 * CIN + ci) * COUT + co];
    float w7 = w[(size_t)(7 * CIN + ci) * COUT + co];
    float w8 = w[(size_t)(8 * CIN + ci) * COUT + co];

    // rows of G g  (G = [[1,0,0],[.5,.5,.5],[.5,-.5,.5],[0,0,1]])
    float r00 = w0, r01 = w1, r02 = w2;
    float r10 = 0.5f * (w0 + w3 + w6), r11 = 0.5f * (w1 + w4 + w7), r12 = 0.5f * (w2 + w5 + w8);
    float r20 = 0.5f * (w0 - w3 + w6), r21 = 0.5f * (w1 - w4 + w7), r22 = 0.5f * (w2 - w5 + w8);
    float r30 = w6, r31 = w7, r32 = w8;

#define WPST(K, V) uwf[(((size_t)(K) * (CIN / 2) + cp) * COUT + co) * 2 + lane] = (V)
#define WPROW(I, A, B, C) \
    WPST((I) * 4 + 0, (A)); \
    WPST((I) * 4 + 1, 0.5f * ((A) + (B) + (C))); \
    WPST((I) * 4 + 2, 0.5f * ((A) - (B) + (C))); \
    WPST((I) * 4 + 3, (C))
    WPROW(0, r00, r01, r02);
    WPROW(1, r10, r11, r12);
    WPROW(2, r20, r21, r22);
    WPROW(3, r30, r31, r32);
#undef WPROW
#undef WPST
}

// ---------------- Winograd F(2x2,3x3) conv + BN + leaky + 2x2 maxpool ----------------
// Block: COUT threads (one cout each), ONE batch, ONE pooled row, TWO pooled cols
// (two 4x4 input tiles sharing a 4x6 raw tile). Per ci-chunk: raw tile load ->
// scalar input transform B^T d B (one (tile,ci) per thread = 2*CHUNK = blockDim)
// -> mainloop: f32x2 lanes = (even ci, odd ci) partial sums, fused U load + FFMA2.
// Inverse transform A^T M A + lane-sum + BN/leaky/pool in scalarized epilogue.
template <int HIN, int WIN, int CIN, int COUT, int HOUT, int WOUT, int CHUNK>
__device__ __forceinline__ void conv_wino_impl(
    const float* __restrict__ in, const float* __restrict__ uwf,
    const float* __restrict__ cb, const float* __restrict__ gg,
    const float* __restrict__ bb, const float* __restrict__ mm,
    const float* __restrict__ mv, float* __restrict__ out)
{
    constexpr int CP = CHUNK / 2;
    constexpr int CPIN = CIN / 2;
    __shared__ __align__(16) float sRaw[4 * 6 * CHUNK];
    __shared__ __align__(16) float sV[16 * CP * 4];   // [k][cp][tile][lane]

    const int c   = threadIdx.x;
    const int px0 = blockIdx.x * 2;
    const int py  = blockIdx.y;
    const int b   = blockIdx.z;

    const float scale = gg[c] * rsqrtf(mv[c] + 1e-5f);
    const float bias  = (cb[c] - mm[c]) * scale + bb[c];

    const int y0 = 2 * py - 1;
    const int x0 = 2 * px0 - 1;
    const float* inb = in + (size_t)b * HIN * WIN * CIN;

    float2 acc0[16], acc1[16];
#pragma unroll
    for (int k = 0; k < 16; k++) {
        acc0[k] = make_float2(0.f, 0.f);
        acc1[k] = make_float2(0.f, 0.f);
    }

    for (int c0 = 0; c0 < CIN; c0 += CHUNK) {
        __syncthreads();   // previous mainloop's sV reads complete

        // ---- raw tile load: [pos][ci], ci innermost (coalesced, conflict-free) ----
        for (int idx = threadIdx.x; idx < 4 * 6 * CHUNK; idx += COUT) {
            int ci   = idx % CHUNK;
            int rest = idx / CHUNK;
            int col  = rest % 6;
            int r    = rest / 6;
            int y = y0 + r, x = x0 + col;
            float v = 0.f;
            if (y >= 0 && y < HIN && x >= 0 && x < WIN)
                v = inb[((size_t)y * WIN + x) * CIN + c0 + ci];
            sRaw[idx] = v;
        }
        __syncthreads();

        // ---- input transform: one (tile, ci) per thread, named scalars only ----
        {
            const int t  = threadIdx.x / CHUNK;      // 2*CHUNK == COUT
            const int ci = threadIdx.x % CHUNK;
            const float* rp = sRaw + 2 * t * CHUNK + ci;
#define DD(R, J) rp[((R) * 6 + (J)) * CHUNK]
            float d00 = DD(0, 0), d01 = DD(0, 1), d02 = DD(0, 2), d03 = DD(0, 3);
            float d10 = DD(1, 0), d11 = DD(1, 1), d12 = DD(1, 2), d13 = DD(1, 3);
            float d20 = DD(2, 0), d21 = DD(2, 1), d22 = DD(2, 2), d23 = DD(2, 3);
            float d30 = DD(3, 0), d31 = DD(3, 1), d32 = DD(3, 2), d33 = DD(3, 3);
#undef DD
            float t00 = d00 - d20, t01 = d01 - d21, t02 = d02 - d22, t03 = d03 - d23;
            float t10 = d10 + d20, t11 = d11 + d21, t12 = d12 + d22, t13 = d13 + d23;
            float t20 = d20 - d10, t21 = d21 - d11, t22 = d22 - d12, t23 = d23 - d13;
            float t30 = d10 - d30, t31 = d11 - d31, t32 = d12 - d32, t33 = d13 - d33;

            float* vp = sV + ((ci >> 1) * 4) + t * 2 + (ci & 1);
#define VST(K, V) vp[(K) * (CP * 4)] = (V)
            VST(0,  t00 - t02); VST(1,  t01 + t02); VST(2,  t02 - t01); VST(3,  t01 - t03);
            VST(4,  t10 - t12); VST(5,  t11 + t12); VST(6,  t12 - t11); VST(7,  t11 - t13);
            VST(8,  t20 - t22); VST(9,  t21 + t22); VST(10, t22 - t21); VST(11, t21 - t23);
            VST(12, t30 - t32); VST(13, t31 + t32); VST(14, t32 - t31); VST(15, t31 - t33);
#undef VST
        }
        __syncthreads();

        // ---- mainloop over ci-pairs (fused scalar U load + FFMA2) ----
        const int cpg0 = c0 / 2;
        for (int cp = 0; cp < CP; cp++) {
#pragma unroll
            for (int k = 0; k < 16; k++) {
                size_t ub = (((size_t)k * CPIN + cpg0 + cp) * COUT + c) * 2;
                float ue = uwf[ub];
                float uo = uwf[ub + 1];
                float2 u2 = make_float2(ue, uo);
                float4 vv = *(const float4*)(sV + (k * CP + cp) * 4);
                acc0[k] = ffma2(make_float2(vv.x, vv.y), u2, acc0[k]);
                acc1[k] = ffma2(make_float2(vv.z, vv.w), u2, acc1[k]);
            }
        }
    }

    // ---- epilogue: inverse transform + lane sum + BN + leaky + pool (scalarized) ----
#define EPILOG(ACC, TT) do { \
    const int px = px0 + (TT); \
    if (px < WOUT) { \
        float2 e0 = fadd2(fadd2(ACC[0], ACC[4]), ACC[8]); \
        float2 e1 = fadd2(fadd2(ACC[1], ACC[5]), ACC[9]); \
        float2 e2 = fadd2(fadd2(ACC[2], ACC[6]), ACC[10]); \
        float2 e3 = fadd2(fadd2(ACC[3], ACC[7]), ACC[11]); \
        float2 f0 = fsub2(fsub2(ACC[4], ACC[8]), ACC[12]); \
        float2 f1 = fsub2(fsub2(ACC[5], ACC[9]), ACC[13]); \
        float2 f2 = fsub2(fsub2(ACC[6], ACC[10]), ACC[14]); \
        float2 f3 = fsub2(fsub2(ACC[7], ACC[11]), ACC[15]); \
        float2 Y00 = fadd2(fadd2(e0, e1), e2); \
        float2 Y01 = fsub2(fsub2(e1, e2), e3); \
        float2 Y10 = fadd2(fadd2(f0, f1), f2); \
        float2 Y11 = fsub2(fsub2(f1, f2), f3); \
        float mx = -1e30f; \
        if (2 * py < HIN) { \
            if (2 * px < WIN) { float rv = fmaf(Y00.x + Y00.y, scale, bias); mx = fmaxf(mx, (rv < 0.f) ? 0.01f * rv : rv); } \
            if (2 * px + 1 < WIN) { float rv = fmaf(Y01.x + Y01.y, scale, bias); mx = fmaxf(mx, (rv < 0.f) ? 0.01f * rv : rv); } \
        } \
        if (2 * py + 1 < HIN) { \
            if (2 * px < WIN) { float rv = fmaf(Y10.x + Y10.y, scale, bias); mx = fmaxf(mx, (rv < 0.f) ? 0.01f * rv : rv); } \
            if (2 * px + 1 < WIN) { float rv = fmaf(Y11.x + Y11.y, scale, bias); mx = fmaxf(mx, (rv < 0.f) ? 0.01f * rv : rv); } \
        } \
        out[(((size_t)b * HOUT + py) * WOUT + px) * COUT + c] = mx; \
    } \
} while (0)
    EPILOG(acc0, 0);
    EPILOG(acc1, 1);
#undef EPILOG
}

__global__ void __launch_bounds__(128) conv_l2(
    const float* __restrict__ cb, const float* __restrict__ g, const float* __restrict__ bb,
    const float* __restrict__ mm, const float* __restrict__ mv)
{
    conv_wino_impl<30, 90, 64, 128, 15, 45, 64>(g_p1, g_uw2, cb, g, bb, mm, mv, g_p2);
}

__global__ void __launch_bounds__(128) conv_l3(
    const float* __restrict__ cb, const float* __restrict__ g, const float* __restrict__ bb,
    const float* __restrict__ mm, const float* __restrict__ mv)
{
    conv_wino_impl<15, 45, 128, 128, 8, 23, 64>(g_p2, g_uw3, cb, g, bb, mm, mv, g_p3);
}

// ---------------- conv1: FFMA2 fused conv+BN+leaky+pool (CIN=1) + inline weight prep ----
__global__ void __launch_bounds__(64) conv_l1(
    const float* __restrict__ in, const float* __restrict__ w,
    const float* __restrict__ cb, const float* __restrict__ gg,
    const float* __restrict__ bb, const float* __restrict__ mm,
    const float* __restrict__ mv,
    const float* __restrict__ w2, const float* __restrict__ w3)
{
    // --- inline Winograd weight prep (first 24576 global threads, one item each) ---
    {
        int gb = (blockIdx.z * gridDim.y + blockIdx.y) * gridDim.x + blockIdx.x;
        int gt = gb * 64 + threadIdx.x;
        if (gt < 64 * 128) {
            wino_xform_one(w2, g_uw2, 64, 128, gt);
        } else if (gt < 64 * 128 + 128 * 128) {
            wino_xform_one(w3, g_uw3, 128, 128, gt - 64 * 128);
        }
    }

    constexpr int HIN = 60, WIN = 180, COUT = 64, HOUT = 30, WOUT = 90, TW = 5;
    constexpr int TC = 2 * TW + 2;
    __shared__ float2 sIn[4 * TC];

    const int c   = threadIdx.x;
    const int pw0 = blockIdx.x * TW;
    const int ph  = blockIdx.y;
    const int b0  = blockIdx.z * 2;

    const float scale = gg[c] * rsqrtf(mv[c] + 1e-5f);
    const float bias  = (cb[c] - mm[c]) * scale + bb[c];

    const int y0 = 2 * ph - 1;
    const int x0 = 2 * pw0 - 1;
    const float* inA = in + (size_t)(b0 + 0) * HIN * WIN;
    const float* inB = in + (size_t)(b0 + 1) * HIN * WIN;

    for (int idx = threadIdx.x; idx < 4 * TC; idx += COUT) {
        int col = idx % TC, r = idx / TC;
        int y = y0 + r, x = x0 + col;
        float a = 0.f, bvv = 0.f;
        if (y >= 0 && y < HIN && x >= 0 && x < WIN) {
            size_t off = (size_t)y * WIN + x;
            a = inA[off]; bvv = inB[off];
        }
        sIn[idx] = make_float2(a, bvv);
    }
    __syncthreads();

    float2 acc[2][2 * TW];
#pragma unroll
    for (int i = 0; i < 2; i++)
#pragma unroll
        for (int jx = 0; jx < 2 * TW; jx++) acc[i][jx] = make_float2(0.f, 0.f);

    float2 w2r[9];
#pragma unroll
    for (int tp = 0; tp < 9; tp++) {
        float wv = w[(size_t)tp * COUT + c];
        w2r[tp] = make_float2(wv, wv);
    }
#pragma unroll
    for (int r = 0; r < 4; r++) {
        float2 rowv[TC];
#pragma unroll
        for (int col = 0; col < TC; col++) rowv[col] = sIn[r * TC + col];
#pragma unroll
        for (int cy = 0; cy < 2; cy++) {
            const int dy = r - cy;
            if (dy >= 0 && dy < 3) {
#pragma unroll
                for (int dx = 0; dx < 3; dx++) {
                    const float2 wv = w2r[dy * 3 + dx];
#pragma unroll
                    for (int cxx = 0; cxx < 2 * TW; cxx++)
                        acc[cy][cxx] = ffma2(rowv[cxx + dx], wv, acc[cy][cxx]);
                }
            }
        }
    }

#pragma unroll
    for (int pl = 0; pl < TW; pl++) {
        int pw = pw0 + pl;
        if (pw < WOUT) {
            float mA = -1e30f, mB = -1e30f;
#pragma unroll
            for (int cy = 0; cy < 2; cy++) {
#pragma unroll
                for (int px = 0; px < 2; px++) {
                    int cxx = 2 * pl + px;
                    float rA = fmaf(acc[cy][cxx].x, scale, bias);
                    float rB = fmaf(acc[cy][cxx].y, scale, bias);
                    rA = (rA < 0.f) ? 0.01f * rA : rA;
                    rB = (rB < 0.f) ? 0.01f * rB : rB;
                    mA = fmaxf(mA, rA);
                    mB = fmaxf(mB, rB);
                }
            }
            size_t o = (((size_t)(b0 + 0) * HOUT + ph) * WOUT + pw) * COUT + c;
            g_p1[o] = mA;
            g_p1[o + (size_t)HOUT * WOUT * COUT] = mB;
        }
    }
}

// ---------------- conv4: direct FFMA2 (R11 proven) ----------------
__global__ void __launch_bounds__(64) conv_l4(
    const float* __restrict__ w, const float* __restrict__ cb,
    const float* __restrict__ gg, const float* __restrict__ bb,
    const float* __restrict__ mm, const float* __restrict__ mv)
{
    constexpr int HIN = 8, WIN = 23, CIN = 128, COUT = 64, HOUT = 4, WOUT = 12, TW = 3, CHUNK = 32;
    constexpr int TC = 2 * TW + 2;
    __shared__ __align__(16) float2 sIn[4 * TC * CHUNK];

    const int c   = threadIdx.x;
    const int pw0 = blockIdx.x * TW;
    const int ph  = blockIdx.y;
    const int b0  = blockIdx.z * 2;

    const float scale = gg[c] * rsqrtf(mv[c] + 1e-5f);
    const float bias  = (cb[c] - mm[c]) * scale + bb[c];

    const int y0 = 2 * ph - 1;
    const int x0 = 2 * pw0 - 1;
    const float* inA = g_p3 + (size_t)(b0 + 0) * HIN * WIN * CIN;
    const float* inB = g_p3 + (size_t)(b0 + 1) * HIN * WIN * CIN;

    float2 acc[2][2 * TW];
#pragma unroll
    for (int i = 0; i < 2; i++)
#pragma unroll
        for (int jx = 0; jx < 2 * TW; jx++) acc[i][jx] = make_float2(0.f, 0.f);

    for (int c0 = 0; c0 < CIN; c0 += CHUNK) {
        __syncthreads();
        for (int idx = threadIdx.x; idx < 4 * TC * CHUNK; idx += COUT) {
            int ci   = idx % CHUNK;
            int rest = idx / CHUNK;
            int col  = rest % TC;
            int r    = rest / TC;
            int y = y0 + r, x = x0 + col;
            float a = 0.f, b = 0.f;
            if (y >= 0 && y < HIN && x >= 0 && x < WIN) {
                size_t off = ((size_t)y * WIN + x) * CIN + c0 + ci;
                a = inA[off];
                b = inB[off];
            }
            sIn[idx] = make_float2(a, b);
        }
        __syncthreads();

        for (int ci = 0; ci < CHUNK; ci += 2) {
            float2 wa[9], wb[9];
#pragma unroll
            for (int tp = 0; tp < 9; tp++) {
                const float* wr = w + ((size_t)tp * CIN + c0 + ci) * COUT + c;
                float va = wr[0];
                float vb = wr[COUT];
                wa[tp] = make_float2(va, va);
                wb[tp] = make_float2(vb, vb);
            }
#pragma unroll
            for (int r = 0; r < 4; r++) {
                float2 ra[TC], rb[TC];
#pragma unroll
                for (int col = 0; col < TC; col++) {
                    float4 t = *(const float4*)(sIn + (r * TC + col) * CHUNK + ci);
                    ra[col] = make_float2(t.x, t.y);
                    rb[col] = make_float2(t.z, t.w);
                }
#pragma unroll
                for (int cy = 0; cy < 2; cy++) {
                    const int dy = r - cy;
                    if (dy >= 0 && dy < 3) {
#pragma unroll
                        for (int dx = 0; dx < 3; dx++) {
                            const float2 wva = wa[dy * 3 + dx];
                            const float2 wvb = wb[dy * 3 + dx];
#pragma unroll
                            for (int cx = 0; cx < 2 * TW; cx++) {
                                acc[cy][cx] = ffma2(ra[cx + dx], wva, acc[cy][cx]);
                                acc[cy][cx] = ffma2(rb[cx + dx], wvb, acc[cy][cx]);
                            }
                        }
                    }
                }
            }
        }
    }

#pragma unroll
    for (int pl = 0; pl < TW; pl++) {
        int pw = pw0 + pl;
        if (pw < WOUT) {
            float mA = -1e30f, mB = -1e30f;
#pragma unroll
            for (int cy = 0; cy < 2; cy++) {
                if (2 * ph + cy < HIN) {
#pragma unroll
                    for (int px = 0; px < 2; px++) {
                        int cx = 2 * pl + px;
                        if (2 * pw0 + cx < WIN) {
                            float rA = fmaf(acc[cy][cx].x, scale, bias);
                            float rB = fmaf(acc[cy][cx].y, scale, bias);
                            rA = (rA < 0.f) ? 0.01f * rA : rA;
                            rB = (rB < 0.f) ? 0.01f * rB : rB;
                            mA = fmaxf(mA, rA);
                            mB = fmaxf(mB, rB);
                        }
                    }
                }
            }
            size_t o = (((size_t)(b0 + 0) * HOUT + ph) * WOUT + pw) * COUT + c;
            g_p4[o] = mA;
            g_p4[o + (size_t)HOUT * WOUT * COUT] = mB;
        }
    }
}

// ---------------- fully fused LSTM (2 layers x 12 steps) + projection ----------------
#define K0 384
#define K1 256

template <int K>
__device__ __forceinline__ void lstm_gates(
    const float* __restrict__ s, const float* __restrict__ W,
    const float* __restrict__ bias, int j, float2 a[4][2])
{
#pragma unroll
    for (int g = 0; g < 4; g++) {
        float bv = bias[g * NH + j];
        a[g][0] = make_float2(bv, bv);
        a[g][1] = make_float2(bv, bv);
    }
    const float4* s4 = (const float4*)s;
#pragma unroll 4
    for (int k = 0; k < K; k++) {
        float4 xv = s4[k];
        float2 xlo = make_float2(xv.x, xv.y);
        float2 xhi = make_float2(xv.z, xv.w);
        const float* Wr = W + (size_t)k * (4 * NH);
#pragma unroll
        for (int g = 0; g < 4; g++) {
            float wv = Wr[g * NH + j];
            float2 w2 = make_float2(wv, wv);
            a[g][0] = ffma2(xlo, w2, a[g][0]);
            a[g][1] = ffma2(xhi, w2, a[g][1]);
        }
    }
}

__global__ void __launch_bounds__(128) lstm_all_kernel(
    const float* __restrict__ lW0, const float* __restrict__ lb0,
    const float* __restrict__ lW1, const float* __restrict__ lb1,
    const float* __restrict__ Wout, const float* __restrict__ bout,
    float* __restrict__ out)
{
    __shared__ float s0[K0 * 4];
    __shared__ float s1[K1 * 4];

    const int tid = threadIdx.x;
    const int j   = tid;
    const int b0  = blockIdx.x * 4;

    float c0[4], c1[4];
#pragma unroll
    for (int bb = 0; bb < 4; bb++) { c0[bb] = 0.f; c1[bb] = 0.f; }

    for (int idx = tid; idx < 128 * 4; idx += 128) {
        s0[(256 + idx / 4) * 4 + (idx & 3)] = 0.f;
        s1[idx] = 0.f;
        s1[128 * 4 + idx] = 0.f;
    }

    for (int t = 0; t < TSTEPS; t++) {
        for (int idx = tid; idx < 4 * 256; idx += 128) {
            int bb = idx >> 8, k = idx & 255;
            int fh = k >> 6, cc = k & 63;
            s0[k * 4 + bb] = g_p4[(((size_t)(b0 + bb) * 4 + fh) * TSTEPS + t) * 64 + cc];
        }
        __syncthreads();

        float2 a0[4][2];
        lstm_gates<K0>(s0, lW0, lb0, j, a0);
        __syncthreads();

        {
            float ai[4] = {a0[0][0].x, a0[0][0].y, a0[0][1].x, a0[0][1].y};
            float aj[4] = {a0[1][0].x, a0[1][0].y, a0[1][1].x, a0[1][1].y};
            float af[4] = {a0[2][0].x, a0[2][0].y, a0[2][1].x, a0[2][1].y};
            float ao[4] = {a0[3][0].x, a0[3][0].y, a0[3][1].x, a0[3][1].y};
#pragma unroll
            for (int bb = 0; bb < 4; bb++) {
                float c = c0[bb] * sigm(af[bb] + 1.f) + sigm(ai[bb]) * tanhf(aj[bb]);
                c0[bb] = c;
                float h = tanhf(c) * sigm(ao[bb]);
                s0[(256 + j) * 4 + bb] = h;
                s1[j * 4 + bb] = h;
            }
        }
        __syncthreads();

        float2 a1[4][2];
        lstm_gates<K1>(s1, lW1, lb1, j, a1);
        __syncthreads();

        {
            float ai[4] = {a1[0][0].x, a1[0][0].y, a1[0][1].x, a1[0][1].y};
            float aj[4] = {a1[1][0].x, a1[1][0].y, a1[1][1].x, a1[1][1].y};
            float af[4] = {a1[2][0].x, a1[2][0].y, a1[2][1].x, a1[2][1].y};
            float ao[4] = {a1[3][0].x, a1[3][0].y, a1[3][1].x, a1[3][1].y};
#pragma unroll
            for (int bb = 0; bb < 4; bb++) {
                float c = c1[bb] * sigm(af[bb] + 1.f) + sigm(ai[bb]) * tanhf(aj[bb]);
                c1[bb] = c;
                s1[(128 + j) * 4 + bb] = tanhf(c) * sigm(ao[bb]);
            }
        }
        __syncthreads();

        for (int idx = tid; idx < 4 * NB; idx += 128) {
            int bb = idx / NB, nb = idx % NB;
            float acc = bout[nb];
#pragma unroll 8
            for (int k = 0; k < NH; k++)
                acc = fmaf(s1[(128 + k) * 4 + bb], Wout[k * NB + nb], acc);
            out[((size_t)t * NBATCH + (b0 + bb)) * NB + nb] = acc;
        }
    }
}

// ---------------- launch ----------------
extern "C" void kernel_launch(void* const* d_in, const int* in_sizes, int n_in,
                              void* d_out, int out_size)
{
    (void)in_sizes; (void)n_in; (void)out_size;
    const float* x = (const float*)d_in[0];
#define LW(i, k) ((const float*)d_in[1 + 6 * (i) + (k)])
    const float* lW0  = (const float*)d_in[25];
    const float* lb0  = (const float*)d_in[26];
    const float* lW1  = (const float*)d_in[27];
    const float* lb1  = (const float*)d_in[28];
    const float* Wout = (const float*)d_in[29];
    const float* bout = (const float*)d_in[30];
    float* out = (float*)d_out;

    // conv1 also performs the Winograd weight transforms for conv2/conv3
    conv_l1<<<dim3(18, 30, NBATCH / 2), 64>>>(x, LW(0, 0), LW(0, 1), LW(0, 2), LW(0, 3),
                                              LW(0, 4), LW(0, 5), LW(1, 0), LW(2, 0));

    conv_l2<<<dim3(23, 15, NBATCH), 128>>>(LW(1, 1), LW(1, 2), LW(1, 3), LW(1, 4), LW(1, 5));
    conv_l3<<<dim3(12, 8, NBATCH), 128>>>(LW(2, 1), LW(2, 2), LW(2, 3), LW(2, 4), LW(2, 5));
    conv_l4<<<dim3(4, 4, NBATCH / 2), 64>>>(LW(3, 0), LW(3, 1), LW(3, 2), LW(3, 3), LW(3, 4), LW(3, 5));

    lstm_all_kernel<<<NBATCH / 4, 128>>>(lW0, lb0, lW1, lb1, Wout, bout, out);
#undef LW
}

// round 16
// speedup vs baseline: 1.8181x; 1.8181x over previous
#include <cuda_runtime.h>
#include <math.h>

#define NBATCH 256
#define NH 128
#define NB 37
#define TSTEPS 12

// ---------------- scratch (device globals; no allocation, NO align attrs) ----------------
static __device__ float g_p1[(size_t)NBATCH * 30 * 90 * 64];   // 177 MB
static __device__ float g_p2[(size_t)NBATCH * 15 * 45 * 128];  //  88 MB
static __device__ float g_p3[(size_t)NBATCH * 8 * 23 * 128];   //  24 MB
static __device__ float g_p4[(size_t)NBATCH * 4 * 12 * 64];    //   3 MB
// Winograd weights U = G g G^T, scalar layout: uwf[((k*CIN)+ci)*COUT + co]
static __device__ float g_uw2[16 * 64 * 128];    // conv2 (512 KB)
static __device__ float g_uw3[16 * 128 * 128];   // conv3 (1 MB)

// ---------------- packed fp32x2 FMA (sm_100+) ----------------
__device__ __forceinline__ float2 ffma2(float2 a, float2 b, float2 c)
{
    float2 d;
    asm("fma.rn.f32x2 %0, %1, %2, %3;"
        : "=l"(reinterpret_cast<unsigned long long&>(d))
        : "l"(reinterpret_cast<unsigned long long&>(a)),
          "l"(reinterpret_cast<unsigned long long&>(b)),
          "l"(reinterpret_cast<unsigned long long&>(c)));
    return d;
}
__device__ __forceinline__ float2 fadd2(float2 a, float2 b) { return make_float2(a.x + b.x, a.y + b.y); }
__device__ __forceinline__ float2 fsub2(float2 a, float2 b) { return make_float2(a.x - b.x, a.y - b.y); }
__device__ __forceinline__ float sigm(float x) { return 1.f / (1.f + expf(-x)); }

// ---------------- Winograd weight transform: one (ci, cout) item, scalar-only ----------------
__device__ __forceinline__ void wino_xform_one(
    const float* __restrict__ w, float* __restrict__ uwf, int CIN, int COUT, int idx)
{
    int co = idx % COUT;
    int ci = idx / COUT;

    float w0 = w[(size_t)(0 * CIN + ci) * COUT + co];
    float w1 = w[(size_t)(1 * CIN + ci) * COUT + co];
    float w2 = w[(size_t)(2 * CIN + ci) * COUT + co];
    float w3 = w[(size_t)(3 * CIN + ci) * COUT + co];
    float w4 = w[(size_t)(4 * CIN + ci) * COUT + co];
    float w5 = w[(size_t)(5 * CIN + ci) * COUT + co];
    float w6 = w[(size_t)(6 * CIN + ci) * COUT + co];
    float w7 = w[(size_t)(7 * CIN + ci) * COUT + co];
    float w8 = w[(size_t)(8 * CIN + ci) * COUT + co];

    // rows of G g  (G = [[1,0,0],[.5,.5,.5],[.5,-.5,.5],[0,0,1]])
    float r00 = w0, r01 = w1, r02 = w2;
    float r10 = 0.5f * (w0 + w3 + w6), r11 = 0.5f * (w1 + w4 + w7), r12 = 0.5f * (w2 + w5 + w8);
    float r20 = 0.5f * (w0 - w3 + w6), r21 = 0.5f * (w1 - w4 + w7), r22 = 0.5f * (w2 - w5 + w8);
    float r30 = w6, r31 = w7, r32 = w8;

#define WPST(K, V) uwf[((size_t)(K) * CIN + ci) * COUT + co] = (V)
#define WPROW(I, A, B, C) \
    WPST((I) * 4 + 0, (A)); \
    WPST((I) * 4 + 1, 0.5f * ((A) + (B) + (C))); \
    WPST((I) * 4 + 2, 0.5f * ((A) - (B) + (C))); \
    WPST((I) * 4 + 3, (C))
    WPROW(0, r00, r01, r02);
    WPROW(1, r10, r11, r12);
    WPROW(2, r20, r21, r22);
    WPROW(3, r30, r31, r32);
#undef WPROW
#undef WPST
}

// ---------------- Winograd F(2x2,3x3) conv + BN + leaky + 2x2 maxpool (v2) ----------------
// Block: COUT(=128) threads, TWO batches in f32x2 lanes, ONE pooled row, FOUR pooled
// cols (4 tiles). Per ci-chunk: raw 4x10 float2 tile load -> input transform B^T d B
// (one (tile,ci) per thread = 4*CHUNK = blockDim) -> mainloop per (ci, k):
// 1 coalesced LDG.32 (U, constant k offsets) + 2 broadcast LDS.128 (V, 4 tiles) +
// 4 FFMA2. Epilogue: inverse transform A^T M A per tile, BN/leaky/pool per lane,
// writes both batch planes. U traffic per block amortized over 8 tile-instances.
template <int HIN, int WIN, int CIN, int COUT, int HOUT, int WOUT, int CHUNK>
__device__ __forceinline__ void conv_wino_impl(
    const float* __restrict__ in, const float* __restrict__ uwf,
    const float* __restrict__ cb, const float* __restrict__ gg,
    const float* __restrict__ bb, const float* __restrict__ mm,
    const float* __restrict__ mv, float* __restrict__ out)
{
    __shared__ __align__(16) float2 sRaw[4 * 10 * CHUNK];
    __shared__ __align__(16) float2 sV[16 * CHUNK * 4];   // [k][ci][tile]

    const int c   = threadIdx.x;
    const int px0 = blockIdx.x * 4;
    const int py  = blockIdx.y;
    const int b0  = blockIdx.z * 2;

    const float scale = gg[c] * rsqrtf(mv[c] + 1e-5f);
    const float bias  = (cb[c] - mm[c]) * scale + bb[c];

    const int y0 = 2 * py - 1;
    const int x0 = 2 * px0 - 1;
    const float* inA = in + (size_t)b0 * HIN * WIN * CIN;
    const float* inB = inA + (size_t)HIN * WIN * CIN;

    float2 a0[16], a1[16], a2[16], a3[16];
#pragma unroll
    for (int k = 0; k < 16; k++) {
        a0[k] = make_float2(0.f, 0.f);
        a1[k] = make_float2(0.f, 0.f);
        a2[k] = make_float2(0.f, 0.f);
        a3[k] = make_float2(0.f, 0.f);
    }

    for (int c0 = 0; c0 < CIN; c0 += CHUNK) {
        __syncthreads();   // previous mainloop's sV reads complete

        // ---- raw tile load: [pos][ci] float2{batchA,batchB}, ci innermost ----
        for (int idx = c; idx < 4 * 10 * CHUNK; idx += COUT) {
            int ci   = idx % CHUNK;
            int rest = idx / CHUNK;
            int col  = rest % 10;
            int r    = rest / 10;
            int y = y0 + r, x = x0 + col;
            float va = 0.f, vb = 0.f;
            if (y >= 0 && y < HIN && x >= 0 && x < WIN) {
                size_t off = ((size_t)y * WIN + x) * CIN + c0 + ci;
                va = inA[off];
                vb = inB[off];
            }
            sRaw[idx] = make_float2(va, vb);
        }
        __syncthreads();

        // ---- input transform: one (tile, ci) per thread (4*CHUNK == COUT) ----
        {
            const int t  = c / CHUNK;
            const int ci = c % CHUNK;
            const float2* rp = sRaw + 2 * t * CHUNK + ci;
#define DD(R, J) rp[((R) * 10 + (J)) * CHUNK]
            float2 d00 = DD(0, 0), d01 = DD(0, 1), d02 = DD(0, 2), d03 = DD(0, 3);
            float2 d10 = DD(1, 0), d11 = DD(1, 1), d12 = DD(1, 2), d13 = DD(1, 3);
            float2 d20 = DD(2, 0), d21 = DD(2, 1), d22 = DD(2, 2), d23 = DD(2, 3);
            float2 d30 = DD(3, 0), d31 = DD(3, 1), d32 = DD(3, 2), d33 = DD(3, 3);
#undef DD
            float2 t00 = fsub2(d00, d20), t01 = fsub2(d01, d21), t02 = fsub2(d02, d22), t03 = fsub2(d03, d23);
            float2 t10 = fadd2(d10, d20), t11 = fadd2(d11, d21), t12 = fadd2(d12, d22), t13 = fadd2(d13, d23);
            float2 t20 = fsub2(d20, d10), t21 = fsub2(d21, d11), t22 = fsub2(d22, d12), t23 = fsub2(d23, d13);
            float2 t30 = fsub2(d10, d30), t31 = fsub2(d11, d31), t32 = fsub2(d12, d32), t33 = fsub2(d13, d33);

            float2* vp = sV + ci * 4 + t;
#define VST(K, V) vp[(K) * (CHUNK * 4)] = (V)
            VST(0,  fsub2(t00, t02)); VST(1,  fadd2(t01, t02)); VST(2,  fsub2(t02, t01)); VST(3,  fsub2(t01, t03));
            VST(4,  fsub2(t10, t12)); VST(5,  fadd2(t11, t12)); VST(6,  fsub2(t12, t11)); VST(7,  fsub2(t11, t13));
            VST(8,  fsub2(t20, t22)); VST(9,  fadd2(t21, t22)); VST(10, fsub2(t22, t21)); VST(11, fsub2(t21, t23));
            VST(12, fsub2(t30, t32)); VST(13, fadd2(t31, t32)); VST(14, fsub2(t32, t31)); VST(15, fsub2(t31, t33));
#undef VST
        }
        __syncthreads();

        // ---- mainloop over ci: per (ci,k) 1 LDG.32 + 2 LDS.128 + 4 FFMA2 ----
        const float* ub = uwf + (size_t)(c0) * COUT + c;   // + ci*COUT + k*CIN*COUT
        const float4* v4 = (const float4*)sV;
        for (int ci = 0; ci < CHUNK; ci++) {
            const float* uci = ub + (size_t)ci * COUT;
#pragma unroll
            for (int k = 0; k < 16; k++) {
                float u = uci[(size_t)k * CIN * COUT];
                float2 u2 = make_float2(u, u);
                float4 vab = v4[2 * (k * CHUNK + ci)];
                float4 vcd = v4[2 * (k * CHUNK + ci) + 1];
                a0[k] = ffma2(make_float2(vab.x, vab.y), u2, a0[k]);
                a1[k] = ffma2(make_float2(vab.z, vab.w), u2, a1[k]);
                a2[k] = ffma2(make_float2(vcd.x, vcd.y), u2, a2[k]);
                a3[k] = ffma2(make_float2(vcd.z, vcd.w), u2, a3[k]);
            }
        }
    }

    // ---- epilogue: inverse transform + BN + leaky + pool, both batch lanes ----
#define EPILOG(ACC, TT) do { \
    const int px = px0 + (TT); \
    if (px < WOUT) { \
        float2 e0 = fadd2(fadd2(ACC[0], ACC[4]), ACC[8]); \
        float2 e1 = fadd2(fadd2(ACC[1], ACC[5]), ACC[9]); \
        float2 e2 = fadd2(fadd2(ACC[2], ACC[6]), ACC[10]); \
        float2 e3 = fadd2(fadd2(ACC[3], ACC[7]), ACC[11]); \
        float2 f0 = fsub2(fsub2(ACC[4], ACC[8]), ACC[12]); \
        float2 f1 = fsub2(fsub2(ACC[5], ACC[9]), ACC[13]); \
        float2 f2 = fsub2(fsub2(ACC[6], ACC[10]), ACC[14]); \
        float2 f3 = fsub2(fsub2(ACC[7], ACC[11]), ACC[15]); \
        float2 Y00 = fadd2(fadd2(e0, e1), e2); \
        float2 Y01 = fsub2(fsub2(e1, e2), e3); \
        float2 Y10 = fadd2(fadd2(f0, f1), f2); \
        float2 Y11 = fsub2(fsub2(f1, f2), f3); \
        float mA = -1e30f, mB = -1e30f; \
        if (2 * py < HIN) { \
            if (2 * px < WIN) { \
                float rA = fmaf(Y00.x, scale, bias); mA = fmaxf(mA, (rA < 0.f) ? 0.01f * rA : rA); \
                float rB = fmaf(Y00.y, scale, bias); mB = fmaxf(mB, (rB < 0.f) ? 0.01f * rB : rB); \
            } \
            if (2 * px + 1 < WIN) { \
                float rA = fmaf(Y01.x, scale, bias); mA = fmaxf(mA, (rA < 0.f) ? 0.01f * rA : rA); \
                float rB = fmaf(Y01.y, scale, bias); mB = fmaxf(mB, (rB < 0.f) ? 0.01f * rB : rB); \
            } \
        } \
        if (2 * py + 1 < HIN) { \
            if (2 * px < WIN) { \
                float rA = fmaf(Y10.x, scale, bias); mA = fmaxf(mA, (rA < 0.f) ? 0.01f * rA : rA); \
                float rB = fmaf(Y10.y, scale, bias); mB = fmaxf(mB, (rB < 0.f) ? 0.01f * rB : rB); \
            } \
            if (2 * px + 1 < WIN) { \
                float rA = fmaf(Y11.x, scale, bias); mA = fmaxf(mA, (rA < 0.f) ? 0.01f * rA : rA); \
                float rB = fmaf(Y11.y, scale, bias); mB = fmaxf(mB, (rB < 0.f) ? 0.01f * rB : rB); \
            } \
        } \
        size_t o = (((size_t)b0 * HOUT + py) * WOUT + px) * COUT + c; \
        out[o] = mA; \
        out[o + (size_t)HOUT * WOUT * COUT] = mB; \
    } \
} while (0)
    EPILOG(a0, 0);
    EPILOG(a1, 1);
    EPILOG(a2, 2);
    EPILOG(a3, 3);
#undef EPILOG
}

__global__ void __launch_bounds__(128) conv_l2(
    const float* __restrict__ cb, const float* __restrict__ g, const float* __restrict__ bb,
    const float* __restrict__ mm, const float* __restrict__ mv)
{
    conv_wino_impl<30, 90, 64, 128, 15, 45, 32>(g_p1, g_uw2, cb, g, bb, mm, mv, g_p2);
}

__global__ void __launch_bounds__(128) conv_l3(
    const float* __restrict__ cb, const float* __restrict__ g, const float* __restrict__ bb,
    const float* __restrict__ mm, const float* __restrict__ mv)
{
    conv_wino_impl<15, 45, 128, 128, 8, 23, 32>(g_p2, g_uw3, cb, g, bb, mm, mv, g_p3);
}

// ---------------- conv1: FFMA2 fused conv+BN+leaky+pool (CIN=1) + inline weight prep ----
__global__ void __launch_bounds__(64) conv_l1(
    const float* __restrict__ in, const float* __restrict__ w,
    const float* __restrict__ cb, const float* __restrict__ gg,
    const float* __restrict__ bb, const float* __restrict__ mm,
    const float* __restrict__ mv,
    const float* __restrict__ w2, const float* __restrict__ w3)
{
    // --- inline Winograd weight prep (first 24576 global threads, one item each) ---
    {
        int gb = (blockIdx.z * gridDim.y + blockIdx.y) * gridDim.x + blockIdx.x;
        int gt = gb * 64 + threadIdx.x;
        if (gt < 64 * 128) {
            wino_xform_one(w2, g_uw2, 64, 128, gt);
        } else if (gt < 64 * 128 + 128 * 128) {
            wino_xform_one(w3, g_uw3, 128, 128, gt - 64 * 128);
        }
    }

    constexpr int HIN = 60, WIN = 180, COUT = 64, HOUT = 30, WOUT = 90, TW = 5;
    constexpr int TC = 2 * TW + 2;
    __shared__ float2 sIn[4 * TC];

    const int c   = threadIdx.x;
    const int pw0 = blockIdx.x * TW;
    const int ph  = blockIdx.y;
    const int b0  = blockIdx.z * 2;

    const float scale = gg[c] * rsqrtf(mv[c] + 1e-5f);
    const float bias  = (cb[c] - mm[c]) * scale + bb[c];

    const int y0 = 2 * ph - 1;
    const int x0 = 2 * pw0 - 1;
    const float* inA = in + (size_t)(b0 + 0) * HIN * WIN;
    const float* inB = in + (size_t)(b0 + 1) * HIN * WIN;

    for (int idx = threadIdx.x; idx < 4 * TC; idx += COUT) {
        int col = idx % TC, r = idx / TC;
        int y = y0 + r, x = x0 + col;
        float a = 0.f, bvv = 0.f;
        if (y >= 0 && y < HIN && x >= 0 && x < WIN) {
            size_t off = (size_t)y * WIN + x;
            a = inA[off]; bvv = inB[off];
        }
        sIn[idx] = make_float2(a, bvv);
    }
    __syncthreads();

    float2 acc[2][2 * TW];
#pragma unroll
    for (int i = 0; i < 2; i++)
#pragma unroll
        for (int jx = 0; jx < 2 * TW; jx++) acc[i][jx] = make_float2(0.f, 0.f);

    float2 w2r[9];
#pragma unroll
    for (int tp = 0; tp < 9; tp++) {
        float wv = w[(size_t)tp * COUT + c];
        w2r[tp] = make_float2(wv, wv);
    }
#pragma unroll
    for (int r = 0; r < 4; r++) {
        float2 rowv[TC];
#pragma unroll
        for (int col = 0; col < TC; col++) rowv[col] = sIn[r * TC + col];
#pragma unroll
        for (int cy = 0; cy < 2; cy++) {
            const int dy = r - cy;
            if (dy >= 0 && dy < 3) {
#pragma unroll
                for (int dx = 0; dx < 3; dx++) {
                    const float2 wv = w2r[dy * 3 + dx];
#pragma unroll
                    for (int cxx = 0; cxx < 2 * TW; cxx++)
                        acc[cy][cxx] = ffma2(rowv[cxx + dx], wv, acc[cy][cxx]);
                }
            }
        }
    }

#pragma unroll
    for (int pl = 0; pl < TW; pl++) {
        int pw = pw0 + pl;
        if (pw < WOUT) {
            float mA = -1e30f, mB = -1e30f;
#pragma unroll
            for (int cy = 0; cy < 2; cy++) {
#pragma unroll
                for (int px = 0; px < 2; px++) {
                    int cxx = 2 * pl + px;
                    float rA = fmaf(acc[cy][cxx].x, scale, bias);
                    float rB = fmaf(acc[cy][cxx].y, scale, bias);
                    rA = (rA < 0.f) ? 0.01f * rA : rA;
                    rB = (rB < 0.f) ? 0.01f * rB : rB;
                    mA = fmaxf(mA, rA);
                    mB = fmaxf(mB, rB);
                }
            }
            size_t o = (((size_t)(b0 + 0) * HOUT + ph) * WOUT + pw) * COUT + c;
            g_p1[o] = mA;
            g_p1[o + (size_t)HOUT * WOUT * COUT] = mB;
        }
    }
}

// ---------------- conv4: direct FFMA2 (R11 proven) ----------------
__global__ void __launch_bounds__(64) conv_l4(
    const float* __restrict__ w, const float* __restrict__ cb,
    const float* __restrict__ gg, const float* __restrict__ bb,
    const float* __restrict__ mm, const float* __restrict__ mv)
{
    constexpr int HIN = 8, WIN = 23, CIN = 128, COUT = 64, HOUT = 4, WOUT = 12, TW = 3, CHUNK = 32;
    constexpr int TC = 2 * TW + 2;
    __shared__ __align__(16) float2 sIn[4 * TC * CHUNK];

    const int c   = threadIdx.x;
    const int pw0 = blockIdx.x * TW;
    const int ph  = blockIdx.y;
    const int b0  = blockIdx.z * 2;

    const float scale = gg[c] * rsqrtf(mv[c] + 1e-5f);
    const float bias  = (cb[c] - mm[c]) * scale + bb[c];

    const int y0 = 2 * ph - 1;
    const int x0 = 2 * pw0 - 1;
    const float* inA = g_p3 + (size_t)(b0 + 0) * HIN * WIN * CIN;
    const float* inB = g_p3 + (size_t)(b0 + 1) * HIN * WIN * CIN;

    float2 acc[2][2 * TW];
#pragma unroll
    for (int i = 0; i < 2; i++)
#pragma unroll
        for (int jx = 0; jx < 2 * TW; jx++) acc[i][jx] = make_float2(0.f, 0.f);

    for (int c0 = 0; c0 < CIN; c0 += CHUNK) {
        __syncthreads();
        for (int idx = threadIdx.x; idx < 4 * TC * CHUNK; idx += COUT) {
            int ci   = idx % CHUNK;
            int rest = idx / CHUNK;
            int col  = rest % TC;
            int r    = rest / TC;
            int y = y0 + r, x = x0 + col;
            float a = 0.f, b = 0.f;
            if (y >= 0 && y < HIN && x >= 0 && x < WIN) {
                size_t off = ((size_t)y * WIN + x) * CIN + c0 + ci;
                a = inA[off];
                b = inB[off];
            }
            sIn[idx] = make_float2(a, b);
        }
        __syncthreads();

        for (int ci = 0; ci < CHUNK; ci += 2) {
            float2 wa[9], wb[9];
#pragma unroll
            for (int tp = 0; tp < 9; tp++) {
                const float* wr = w + ((size_t)tp * CIN + c0 + ci) * COUT + c;
                float va = wr[0];
                float vb = wr[COUT];
                wa[tp] = make_float2(va, va);
                wb[tp] = make_float2(vb, vb);
            }
#pragma unroll
            for (int r = 0; r < 4; r++) {
                float2 ra[TC], rb[TC];
#pragma unroll
                for (int col = 0; col < TC; col++) {
                    float4 t = *(const float4*)(sIn + (r * TC + col) * CHUNK + ci);
                    ra[col] = make_float2(t.x, t.y);
                    rb[col] = make_float2(t.z, t.w);
                }
#pragma unroll
                for (int cy = 0; cy < 2; cy++) {
                    const int dy = r - cy;
                    if (dy >= 0 && dy < 3) {
#pragma unroll
                        for (int dx = 0; dx < 3; dx++) {
                            const float2 wva = wa[dy * 3 + dx];
                            const float2 wvb = wb[dy * 3 + dx];
#pragma unroll
                            for (int cx = 0; cx < 2 * TW; cx++) {
                                acc[cy][cx] = ffma2(ra[cx + dx], wva, acc[cy][cx]);
                                acc[cy][cx] = ffma2(rb[cx + dx], wvb, acc[cy][cx]);
                            }
                        }
                    }
                }
            }
        }
    }

#pragma unroll
    for (int pl = 0; pl < TW; pl++) {
        int pw = pw0 + pl;
        if (pw < WOUT) {
            float mA = -1e30f, mB = -1e30f;
#pragma unroll
            for (int cy = 0; cy < 2; cy++) {
                if (2 * ph + cy < HIN) {
#pragma unroll
                    for (int px = 0; px < 2; px++) {
                        int cx = 2 * pl + px;
                        if (2 * pw0 + cx < WIN) {
                            float rA = fmaf(acc[cy][cx].x, scale, bias);
                            float rB = fmaf(acc[cy][cx].y, scale, bias);
                            rA = (rA < 0.f) ? 0.01f * rA : rA;
                            rB = (rB < 0.f) ? 0.01f * rB : rB;
                            mA = fmaxf(mA, rA);
                            mB = fmaxf(mB, rB);
                        }
                    }
                }
            }
            size_t o = (((size_t)(b0 + 0) * HOUT + ph) * WOUT + pw) * COUT + c;
            g_p4[o] = mA;
            g_p4[o + (size_t)HOUT * WOUT * COUT] = mB;
        }
    }
}

// ---------------- fully fused LSTM (2 layers x 12 steps) + projection ----------------
#define K0 384
#define K1 256

template <int K>
__device__ __forceinline__ void lstm_gates(
    const float* __restrict__ s, const float* __restrict__ W,
    const float* __restrict__ bias, int j, float2 a[4][2])
{
#pragma unroll
    for (int g = 0; g < 4; g++) {
        float bv = bias[g * NH + j];
        a[g][0] = make_float2(bv, bv);
        a[g][1] = make_float2(bv, bv);
    }
    const float4* s4 = (const float4*)s;
#pragma unroll 4
    for (int k = 0; k < K; k++) {
        float4 xv = s4[k];
        float2 xlo = make_float2(xv.x, xv.y);
        float2 xhi = make_float2(xv.z, xv.w);
        const float* Wr = W + (size_t)k * (4 * NH);
#pragma unroll
        for (int g = 0; g < 4; g++) {
            float wv = Wr[g * NH + j];
            float2 w2 = make_float2(wv, wv);
            a[g][0] = ffma2(xlo, w2, a[g][0]);
            a[g][1] = ffma2(xhi, w2, a[g][1]);
        }
    }
}

__global__ void __launch_bounds__(128) lstm_all_kernel(
    const float* __restrict__ lW0, const float* __restrict__ lb0,
    const float* __restrict__ lW1, const float* __restrict__ lb1,
    const float* __restrict__ Wout, const float* __restrict__ bout,
    float* __restrict__ out)
{
    __shared__ float s0[K0 * 4];
    __shared__ float s1[K1 * 4];

    const int tid = threadIdx.x;
    const int j   = tid;
    const int b0  = blockIdx.x * 4;

    float c0[4], c1[4];
#pragma unroll
    for (int bb = 0; bb < 4; bb++) { c0[bb] = 0.f; c1[bb] = 0.f; }

    for (int idx = tid; idx < 128 * 4; idx += 128) {
        s0[(256 + idx / 4) * 4 + (idx & 3)] = 0.f;
        s1[idx] = 0.f;
        s1[128 * 4 + idx] = 0.f;
    }

    for (int t = 0; t < TSTEPS; t++) {
        for (int idx = tid; idx < 4 * 256; idx += 128) {
            int bb = idx >> 8, k = idx & 255;
            int fh = k >> 6, cc = k & 63;
            s0[k * 4 + bb] = g_p4[(((size_t)(b0 + bb) * 4 + fh) * TSTEPS + t) * 64 + cc];
        }
        __syncthreads();

        float2 a0[4][2];
        lstm_gates<K0>(s0, lW0, lb0, j, a0);
        __syncthreads();

        {
            float ai[4] = {a0[0][0].x, a0[0][0].y, a0[0][1].x, a0[0][1].y};
            float aj[4] = {a0[1][0].x, a0[1][0].y, a0[1][1].x, a0[1][1].y};
            float af[4] = {a0[2][0].x, a0[2][0].y, a0[2][1].x, a0[2][1].y};
            float ao[4] = {a0[3][0].x, a0[3][0].y, a0[3][1].x, a0[3][1].y};
#pragma unroll
            for (int bb = 0; bb < 4; bb++) {
                float c = c0[bb] * sigm(af[bb] + 1.f) + sigm(ai[bb]) * tanhf(aj[bb]);
                c0[bb] = c;
                float h = tanhf(c) * sigm(ao[bb]);
                s0[(256 + j) * 4 + bb] = h;
                s1[j * 4 + bb] = h;
            }
        }
        __syncthreads();

        float2 a1[4][2];
        lstm_gates<K1>(s1, lW1, lb1, j, a1);
        __syncthreads();

        {
            float ai[4] = {a1[0][0].x, a1[0][0].y, a1[0][1].x, a1[0][1].y};
            float aj[4] = {a1[1][0].x, a1[1][0].y, a1[1][1].x, a1[1][1].y};
            float af[4] = {a1[2][0].x, a1[2][0].y, a1[2][1].x, a1[2][1].y};
            float ao[4] = {a1[3][0].x, a1[3][0].y, a1[3][1].x, a1[3][1].y};
#pragma unroll
            for (int bb = 0; bb < 4; bb++) {
                float c = c1[bb] * sigm(af[bb] + 1.f) + sigm(ai[bb]) * tanhf(aj[bb]);
                c1[bb] = c;
                s1[(128 + j) * 4 + bb] = tanhf(c) * sigm(ao[bb]);
            }
        }
        __syncthreads();

        for (int idx = tid; idx < 4 * NB; idx += 128) {
            int bb = idx / NB, nb = idx % NB;
            float acc = bout[nb];
#pragma unroll 8
            for (int k = 0; k < NH; k++)
                acc = fmaf(s1[(128 + k) * 4 + bb], Wout[k * NB + nb], acc);
            out[((size_t)t * NBATCH + (b0 + bb)) * NB + nb] = acc;
        }
    }
}

// ---------------- launch ----------------
extern "C" void kernel_launch(void* const* d_in, const int* in_sizes, int n_in,
                              void* d_out, int out_size)
{
    (void)in_sizes; (void)n_in; (void)out_size;
    const float* x = (const float*)d_in[0];
#define LW(i, k) ((const float*)d_in[1 + 6 * (i) + (k)])
    const float* lW0  = (const float*)d_in[25];
    const float* lb0  = (const float*)d_in[26];
    const float* lW1  = (const float*)d_in[27];
    const float* lb1  = (const float*)d_in[28];
    const float* Wout = (const float*)d_in[29];
    const float* bout = (const float*)d_in[30];
    float* out = (float*)d_out;

    // conv1 also performs the Winograd weight transforms for conv2/conv3
    conv_l1<<<dim3(18, 30, NBATCH / 2), 64>>>(x, LW(0, 0), LW(0, 1), LW(0, 2), LW(0, 3),
                                              LW(0, 4), LW(0, 5), LW(1, 0), LW(2, 0));

    // Winograd v2: 4 pooled cols + 2 batches per block (8x tile reuse of U)
    conv_l2<<<dim3(12, 15, NBATCH / 2), 128>>>(LW(1, 1), LW(1, 2), LW(1, 3), LW(1, 4), LW(1, 5));
    conv_l3<<<dim3(6, 8, NBATCH / 2), 128>>>(LW(2, 1), LW(2, 2), LW(2, 3), LW(2, 4), LW(2, 5));
    conv_l4<<<dim3(4, 4, NBATCH / 2), 64>>>(LW(3, 0), LW(3, 1), LW(3, 2), LW(3, 3), LW(3, 4), LW(3, 5));

    lstm_all_kernel<<<NBATCH / 4, 128>>>(lW0, lb0, lW1, lb1, Wout, bout, out);
#undef LW
}

// round 17
// speedup vs baseline: 1.8224x; 1.0024x over previous
#include <cuda_runtime.h>
#include <math.h>

#define NBATCH 256
#define NH 128
#define NB 37
#define TSTEPS 12

// ---------------- scratch (device globals; no allocation) ----------------
static __device__ float g_p1[(size_t)NBATCH * 30 * 90 * 64];   // 177 MB
static __device__ float g_p2[(size_t)NBATCH * 15 * 45 * 128];  //  88 MB
static __device__ float g_p3[(size_t)NBATCH * 8 * 23 * 128];   //  24 MB
static __device__ float g_p4[(size_t)NBATCH * 4 * 12 * 64];    //   3 MB

// ---------------- packed fp32x2 FMA (sm_100+) ----------------
__device__ __forceinline__ float2 ffma2(float2 a, float2 b, float2 c)
{
    float2 d;
    asm("fma.rn.f32x2 %0, %1, %2, %3;"
        : "=l"(reinterpret_cast<unsigned long long&>(d))
        : "l"(reinterpret_cast<unsigned long long&>(a)),
          "l"(reinterpret_cast<unsigned long long&>(b)),
          "l"(reinterpret_cast<unsigned long long&>(c)));
    return d;
}

// ---------------- fused conv3x3 + bias + BN + leakyrelu + maxpool2x2 ----------------
// Batch-PAIRED (2 batches/block, float2 smem, packed fma.rn.f32x2), ci-CHUNKED,
// and ci-PAIR-UNROLLED: smem layout [pos][ci] (conflict-free); one broadcast
// LDS.128 at [(pos)*CHUNK + ci] yields BOTH ci and ci+1 float2 values, halving
// shared loads; the 18 weight LDGs per pair issue back-to-back (MLP).
// Block: COUT threads (one per output channel), TW pooled cols of one pooled row.
template <int HIN, int WIN, int CIN, int COUT, int HOUT, int WOUT, int TW, int CHUNK>
__device__ __forceinline__ void conv_block_impl(
    const float* __restrict__ in, const float* __restrict__ w,
    const float* __restrict__ cb, const float* __restrict__ gg,
    const float* __restrict__ bb, const float* __restrict__ mm,
    const float* __restrict__ mv, float* __restrict__ out)
{
    constexpr int TC = 2 * TW + 2;
    __shared__ __align__(16) float2 sIn[4 * TC * CHUNK];

    const int c   = threadIdx.x;
    const int pw0 = blockIdx.x * TW;
    const int ph  = blockIdx.y;
    const int b0  = blockIdx.z * 2;          // batch pair

    const float scale = gg[c] * rsqrtf(mv[c] + 1e-5f);
    const float bias  = (cb[c] - mm[c]) * scale + bb[c];

    const int y0 = 2 * ph - 1;
    const int x0 = 2 * pw0 - 1;
    const float* inA = in + (size_t)(b0 + 0) * HIN * WIN * CIN;
    const float* inB = in + (size_t)(b0 + 1) * HIN * WIN * CIN;

    float2 acc[2][2 * TW];
#pragma unroll
    for (int i = 0; i < 2; i++)
#pragma unroll
        for (int jx = 0; jx < 2 * TW; jx++) acc[i][jx] = make_float2(0.f, 0.f);

    for (int c0 = 0; c0 < CIN; c0 += CHUNK) {
        __syncthreads();   // previous chunk fully consumed

        // cooperative tile load (ci innermost -> coalesced gmem, conflict-free STS)
        for (int idx = threadIdx.x; idx < 4 * TC * CHUNK; idx += COUT) {
            int ci   = (CHUNK == 1) ? 0 : (idx % CHUNK);
            int rest = (CHUNK == 1) ? idx : (idx / CHUNK);
            int col  = rest % TC;
            int r    = rest / TC;
            int y = y0 + r, x = x0 + col;
            float a = 0.f, b = 0.f;
            if (y >= 0 && y < HIN && x >= 0 && x < WIN) {
                size_t off = ((size_t)y * WIN + x) * CIN + c0 + ci;
                a = inA[off];
                b = inB[off];
            }
            sIn[idx] = make_float2(a, b);
        }
        __syncthreads();

        if (CHUNK == 1) {
            // scalar path (conv1: CIN=1)
            float2 w2[9];
#pragma unroll
            for (int tp = 0; tp < 9; tp++) {
                float wv = w[((size_t)tp * CIN + c0) * COUT + c];
                w2[tp] = make_float2(wv, wv);
            }
#pragma unroll
            for (int r = 0; r < 4; r++) {
                float2 rowv[TC];
#pragma unroll
                for (int col = 0; col < TC; col++) rowv[col] = sIn[r * TC + col];
#pragma unroll
                for (int cy = 0; cy < 2; cy++) {
                    const int dy = r - cy;
                    if (dy >= 0 && dy < 3) {
#pragma unroll
                        for (int dx = 0; dx < 3; dx++) {
                            const float2 wv = w2[dy * 3 + dx];
#pragma unroll
                            for (int cx = 0; cx < 2 * TW; cx++)
                                acc[cy][cx] = ffma2(rowv[cx + dx], wv, acc[cy][cx]);
                        }
                    }
                }
            }
        } else {
            // ci-pair path: 18 batched weight LDGs, paired LDS.128 row reads
            for (int ci = 0; ci < CHUNK; ci += 2) {
                float2 wa[9], wb[9];
#pragma unroll
                for (int tp = 0; tp < 9; tp++) {
                    const float* wr = w + ((size_t)tp * CIN + c0 + ci) * COUT + c;
                    float va = wr[0];
                    float vb = wr[COUT];
                    wa[tp] = make_float2(va, va);
                    wb[tp] = make_float2(vb, vb);
                }
#pragma unroll
                for (int r = 0; r < 4; r++) {
                    float2 ra[TC], rb[TC];
#pragma unroll
                    for (int col = 0; col < TC; col++) {
                        float4 t = *(const float4*)(sIn + (r * TC + col) * CHUNK + ci);
                        ra[col] = make_float2(t.x, t.y);
                        rb[col] = make_float2(t.z, t.w);
                    }
#pragma unroll
                    for (int cy = 0; cy < 2; cy++) {
                        const int dy = r - cy;
                        if (dy >= 0 && dy < 3) {
#pragma unroll
                            for (int dx = 0; dx < 3; dx++) {
                                const float2 wva = wa[dy * 3 + dx];
                                const float2 wvb = wb[dy * 3 + dx];
#pragma unroll
                                for (int cx = 0; cx < 2 * TW; cx++) {
                                    acc[cy][cx] = ffma2(ra[cx + dx], wva, acc[cy][cx]);
                                    acc[cy][cx] = ffma2(rb[cx + dx], wvb, acc[cy][cx]);
                                }
                            }
                        }
                    }
                }
            }
        }
    }

    // epilogue: BN affine + leaky relu + 2x2 SAME maxpool, both batches
#pragma unroll
    for (int pl = 0; pl < TW; pl++) {
        int pw = pw0 + pl;
        if (pw < WOUT) {
            float mA = -1e30f, mB = -1e30f;
#pragma unroll
            for (int cy = 0; cy < 2; cy++) {
                if (2 * ph + cy < HIN) {
#pragma unroll
                    for (int px = 0; px < 2; px++) {
                        int cx = 2 * pl + px;
                        if (2 * pw0 + cx < WIN) {
                            float rA = fmaf(acc[cy][cx].x, scale, bias);
                            float rB = fmaf(acc[cy][cx].y, scale, bias);
                            rA = (rA < 0.f) ? 0.01f * rA : rA;
                            rB = (rB < 0.f) ? 0.01f * rB : rB;
                            mA = fmaxf(mA, rA);
                            mB = fmaxf(mB, rB);
                        }
                    }
                }
            }
            size_t o = (((size_t)(b0 + 0) * HOUT + ph) * WOUT + pw) * COUT + c;
            out[o] = mA;
            out[o + (size_t)HOUT * WOUT * COUT] = mB;
        }
    }
}

__global__ void __launch_bounds__(64) conv_l1(
    const float* __restrict__ x, const float* __restrict__ w, const float* __restrict__ cb,
    const float* __restrict__ g, const float* __restrict__ bb, const float* __restrict__ mm,
    const float* __restrict__ mv)
{
    conv_block_impl<60, 180, 1, 64, 30, 90, 5, 1>(x, w, cb, g, bb, mm, mv, g_p1);
}

__global__ void __launch_bounds__(128) conv_l2(
    const float* __restrict__ w, const float* __restrict__ cb,
    const float* __restrict__ g, const float* __restrict__ bb, const float* __restrict__ mm,
    const float* __restrict__ mv)
{
    conv_block_impl<30, 90, 64, 128, 15, 45, 5, 32>(g_p1, w, cb, g, bb, mm, mv, g_p2);
}

__global__ void __launch_bounds__(128) conv_l3(
    const float* __restrict__ w, const float* __restrict__ cb,
    const float* __restrict__ g, const float* __restrict__ bb, const float* __restrict__ mm,
    const float* __restrict__ mv)
{
    conv_block_impl<15, 45, 128, 128, 8, 23, 5, 32>(g_p2, w, cb, g, bb, mm, mv, g_p3);
}

__global__ void __launch_bounds__(64) conv_l4(
    const float* __restrict__ w, const float* __restrict__ cb,
    const float* __restrict__ g, const float* __restrict__ bb, const float* __restrict__ mm,
    const float* __restrict__ mv)
{
    // TW=2 -> grid (6,4,128)=3072 blocks: lifts grid-limited occupancy further (R10 trend)
    conv_block_impl<8, 23, 128, 64, 4, 12, 2, 32>(g_p3, w, cb, g, bb, mm, mv, g_p4);
}

// ---------------- fully fused LSTM (2 layers x 12 steps) + projection ----------------
// v2: TWO batches per block (128 blocks / 512 warps) for 2x latency hiding;
// f32x2 lanes carry the 2 batches. smem layout [k][bb], bb=2 -> broadcast LDS.64.
#define K0 384
#define K1 256

__device__ __forceinline__ float sigm(float x) { return 1.f / (1.f + expf(-x)); }

template <int K>
__device__ __forceinline__ void lstm_gates2(
    const float* __restrict__ s, const float* __restrict__ W,
    const float* __restrict__ bias, int j, float2 a[4])
{
#pragma unroll
    for (int g = 0; g < 4; g++) {
        float bv = bias[g * NH + j];
        a[g] = make_float2(bv, bv);
    }
    const float2* s2 = (const float2*)s;
#pragma unroll 4
    for (int k = 0; k < K; k++) {
        float2 xv = s2[k];
        const float* Wr = W + (size_t)k * (4 * NH);
#pragma unroll
        for (int g = 0; g < 4; g++) {
            float wv = Wr[g * NH + j];
            a[g] = ffma2(xv, make_float2(wv, wv), a[g]);
        }
    }
}

__global__ void __launch_bounds__(128) lstm_all_kernel(
    const float* __restrict__ lW0, const float* __restrict__ lb0,
    const float* __restrict__ lW1, const float* __restrict__ lb1,
    const float* __restrict__ Wout, const float* __restrict__ bout,
    float* __restrict__ out)
{
    __shared__ float s0[K0 * 2];   // [xt(256) | h0(128)] x 2 batches, layout [k][bb]
    __shared__ float s1[K1 * 2];   // [h0(128) | h1(128)] x 2 batches

    const int tid = threadIdx.x;
    const int j   = tid;           // hidden unit
    const int b0  = blockIdx.x * 2;

    float c0[2], c1[2];
    c0[0] = 0.f; c0[1] = 0.f; c1[0] = 0.f; c1[1] = 0.f;

    // zero h0/h1 regions
    for (int idx = tid; idx < 128 * 2; idx += 128) {
        s0[(256 + idx / 2) * 2 + (idx & 1)] = 0.f;
        s1[idx] = 0.f;                     // h0 region
        s1[128 * 2 + idx] = 0.f;           // h1 region
    }

    for (int t = 0; t < TSTEPS; t++) {
        // fill xt from conv features: x[t][b][fh*64+cc] = p4[b][fh][t][cc]
        for (int idx = tid; idx < 2 * 256; idx += 128) {
            int bb = idx >> 8, k = idx & 255;
            int fh = k >> 6, cc = k & 63;
            s0[k * 2 + bb] = g_p4[(((size_t)(b0 + bb) * 4 + fh) * TSTEPS + t) * 64 + cc];
        }
        __syncthreads();

        // ---- layer 0 ----
        float2 a0[4];
        lstm_gates2<K0>(s0, lW0, lb0, j, a0);
        __syncthreads();

        {
#pragma unroll
            for (int bb = 0; bb < 2; bb++) {
                float ai = bb ? a0[0].y : a0[0].x;
                float aj = bb ? a0[1].y : a0[1].x;
                float af = bb ? a0[2].y : a0[2].x;
                float ao = bb ? a0[3].y : a0[3].x;
                float c = c0[bb] * sigm(af + 1.f) + sigm(ai) * tanhf(aj);
                c0[bb] = c;
                float h = tanhf(c) * sigm(ao);
                s0[(256 + j) * 2 + bb] = h;
                s1[j * 2 + bb] = h;
            }
        }
        __syncthreads();

        // ---- layer 1 ----
        float2 a1[4];
        lstm_gates2<K1>(s1, lW1, lb1, j, a1);
        __syncthreads();

        {
#pragma unroll
            for (int bb = 0; bb < 2; bb++) {
                float ai = bb ? a1[0].y : a1[0].x;
                float aj = bb ? a1[1].y : a1[1].x;
                float af = bb ? a1[2].y : a1[2].x;
                float ao = bb ? a1[3].y : a1[3].x;
                float c = c1[bb] * sigm(af + 1.f) + sigm(ai) * tanhf(aj);
                c1[bb] = c;
                s1[(128 + j) * 2 + bb] = tanhf(c) * sigm(ao);
            }
        }
        __syncthreads();

        // ---- projection: logits[t, b0+bb, nb] = h1 . Wout[:, nb] + bout ----
        for (int idx = tid; idx < 2 * NB; idx += 128) {
            int bb = idx / NB, nb = idx % NB;
            float acc = bout[nb];
#pragma unroll 8
            for (int k = 0; k < NH; k++)
                acc = fmaf(s1[(128 + k) * 2 + bb], Wout[k * NB + nb], acc);
            out[((size_t)t * NBATCH + (b0 + bb)) * NB + nb] = acc;
        }
        // next-iteration barriers protect s1-h1 before overwrite
    }
}

// ---------------- launch ----------------
extern "C" void kernel_launch(void* const* d_in, const int* in_sizes, int n_in,
                              void* d_out, int out_size)
{
    (void)in_sizes; (void)n_in; (void)out_size;
    const float* x = (const float*)d_in[0];
#define LW(i, k) ((const float*)d_in[1 + 6 * (i) + (k)])
    const float* lW0  = (const float*)d_in[25];
    const float* lb0  = (const float*)d_in[26];
    const float* lW1  = (const float*)d_in[27];
    const float* lb1  = (const float*)d_in[28];
    const float* Wout = (const float*)d_in[29];
    const float* bout = (const float*)d_in[30];
    float* out = (float*)d_out;

    conv_l1<<<dim3(18, 30, NBATCH / 2), 64>>>(x, LW(0, 0), LW(0, 1), LW(0, 2), LW(0, 3), LW(0, 4), LW(0, 5));
    conv_l2<<<dim3(9, 15, NBATCH / 2), 128>>>(LW(1, 0), LW(1, 1), LW(1, 2), LW(1, 3), LW(1, 4), LW(1, 5));
    conv_l3<<<dim3(5, 8, NBATCH / 2), 128>>>(LW(2, 0), LW(2, 1), LW(2, 2), LW(2, 3), LW(2, 4), LW(2, 5));
    conv_l4<<<dim3(6, 4, NBATCH / 2), 64>>>(LW(3, 0), LW(3, 1), LW(3, 2), LW(3, 3), LW(3, 4), LW(3, 5));

    lstm_all_kernel<<<NBATCH / 2, 128>>>(lW0, lb0, lW1, lb1, Wout, bout, out);
#undef LW
}